// round 15
// baseline (speedup 1.0000x reference)
#include <cuda_runtime.h>
#include <cstdint>
#include <cstddef>

// Problem dims (fixed by the reference)
#define Bt 1024
#define Tt 512
#define Ii 45
#define Hh 128
#define Oo 45

#define NTH 256
#define NBMAX 4
typedef unsigned long long ull;

// 256 MB scratch: xe[bt][j] = b_ih[j] + b_hh[j] + sum_i x[bt][i]*W_ih[j][i]
__device__ float xe_buf[(size_t)Bt * Tt * Hh];

__device__ __forceinline__ void fma2(ull& acc, ull a, ull b) {
    asm("fma.rn.f32x2 %0, %1, %2, %0;" : "+l"(acc) : "l"(a), "l"(b));
}
__device__ __forceinline__ float2 unpack2(ull d) {
    unsigned lo, hi;
    asm("mov.b64 {%0, %1}, %2;" : "=r"(lo), "=r"(hi) : "l"(d));
    return make_float2(__uint_as_float(lo), __uint_as_float(hi));
}
__device__ __forceinline__ ull pack2f(float lo, float hi) {
    ull d;
    asm("mov.b64 %0, {%1, %2};" : "=l"(d)
        : "r"(__float_as_uint(lo)), "r"(__float_as_uint(hi)));
    return d;
}

// tanh(x) = 1 - 2/(exp(2x)+1): ~1e-6 abs err, exact +/-1 saturation.
__device__ __forceinline__ float fast_tanh(float x) {
    float e = __expf(2.0f * x);
    return 1.0f - __fdividef(2.0f, e + 1.0f);
}

// ============================================================================
// Pre-pass (unchanged from R14)
// ============================================================================
__global__ void __launch_bounds__(NTH, 2)
xe_prepass_kernel(const float* __restrict__ x,
                  const float* __restrict__ W_ih,
                  const float* __restrict__ b_ih,
                  const float* __restrict__ b_hh)
{
    __shared__ float xs[128 * 48];
    __shared__ ull   wp2[24 * 128];

    const int tid = threadIdx.x;
    const int jp  = tid & 63, btg = tid >> 6;
    const int j0  = 2 * jp, j1 = j0 + 1;
    const size_t btBase = (size_t)blockIdx.x * 128;

    for (int idx = tid; idx < 128 * 48; idx += NTH) {
        const int btl = idx / 48, ii = idx - btl * 48;
        xs[idx] = (ii < Ii) ? x[(btBase + btl) * Ii + ii] : 0.0f;
    }
    for (int idx = tid; idx < 128 * 24; idx += NTH) {
        const int jj = idx / 24, p = idx - jj * 24;
        const int ia = 2 * p, ib = ia + 1;
        const float w0 = (ia < Ii) ? W_ih[jj * Ii + ia] : 0.0f;
        const float w1 = (ib < Ii) ? W_ih[jj * Ii + ib] : 0.0f;
        wp2[p * 128 + jj] = pack2f(w0, w1);
    }
    const float bi0 = b_ih[j0] + b_hh[j0];
    const float bi1 = b_ih[j1] + b_hh[j1];
    __syncthreads();

    ull wA[24], wB[24];
    #pragma unroll
    for (int p = 0; p < 24; ++p) {
        wA[p] = wp2[p * 128 + j0];
        wB[p] = wp2[p * 128 + j1];
    }

    for (int c = 0; c < 8; ++c) {
        const int bt0 = btg * 32 + c * 4;
        ull aA[4] = {0ull, 0ull, 0ull, 0ull};
        ull aB[4] = {0ull, 0ull, 0ull, 0ull};

        #pragma unroll
        for (int q = 0; q < 12; ++q) {
            #pragma unroll
            for (int r = 0; r < 4; ++r) {
                const ulonglong2 v = *reinterpret_cast<const ulonglong2*>(
                    xs + (bt0 + r) * 48 + q * 4);
                fma2(aA[r], wA[2 * q], v.x); fma2(aA[r], wA[2 * q + 1], v.y);
                fma2(aB[r], wB[2 * q], v.x); fma2(aB[r], wB[2 * q + 1], v.y);
            }
        }
        #pragma unroll
        for (int r = 0; r < 4; ++r) {
            const float2 fA = unpack2(aA[r]);
            const float2 fB = unpack2(aB[r]);
            float2 o;
            o.x = bi0 + fA.x + fA.y;
            o.y = bi1 + fB.x + fB.y;
            *reinterpret_cast<float2*>(
                xe_buf + (btBase + bt0 + r) * Hh + j0) = o;
        }
    }
}

// ============================================================================
// Recurrence loop v5: R14 structure + manual t-unroll x2 (compile-time cur),
// branch-free finish (own row posted too), strength-reduced xe pointer.
// ============================================================================

// One half-step with compile-time CUR (0 or 1). hc/hn/part bases fold to
// loop-invariant registers; inner addressing is all immediates.
template <int NB, int CUR>
__device__ __forceinline__ void rnn_step(
    int t, int grp, int j0, bool fin,
    const ull (&wk)[4][8],
    float* hT, float* part, float* postp,
    const float* xe_p, float4& xe_cur)
{
    const float* hc = hT + CUR * (NBMAX * Hh) + grp * 16;

    // Prefetch next step's xe (finishing warps; hidden behind FMAs)
    float4 xe_nxt = make_float4(0.f, 0.f, 0.f, 0.f);
    if (fin && t + 1 < Tt)
        xe_nxt = *reinterpret_cast<const float4*>(xe_p + Hh);

    // acc[jj][r]: packed (even-k, odd-k) partial sums
    ull acc[4][NB];
    #pragma unroll
    for (int jj = 0; jj < 4; ++jj)
        #pragma unroll
        for (int r = 0; r < NB; ++r) acc[jj][r] = 0ull;

    // Inner: 4 k-quads x NB rows; each broadcast LDS.128 feeds 8 fma2
    #pragma unroll
    for (int q = 0; q < 4; ++q) {
        #pragma unroll
        for (int r = 0; r < NB; ++r) {
            const ulonglong2 v =
                *reinterpret_cast<const ulonglong2*>(hc + r * Hh + q * 4);
            #pragma unroll
            for (int jj = 0; jj < 4; ++jj) {
                fma2(acc[jj][r], wk[jj][2 * q], v.x);
                fma2(acc[jj][r], wk[jj][2 * q + 1], v.y);
            }
        }
    }

    // Collapse packed lanes to scalars; post float4 partials for ALL rows
    #pragma unroll
    for (int r = 0; r < NB; ++r) {
        float4 s;
        { const float2 f = unpack2(acc[0][r]); s.x = f.x + f.y; }
        { const float2 f = unpack2(acc[1][r]); s.y = f.x + f.y; }
        { const float2 f = unpack2(acc[2][r]); s.z = f.x + f.y; }
        { const float2 f = unpack2(acc[3][r]); s.w = f.x + f.y; }
        *reinterpret_cast<float4*>(postp + r * Hh) = s;
    }
    __syncthreads();

    // Finish row grp: branch-free sum of all 8 groups' partials
    if (fin) {
        const float* pr = part + grp * Hh + j0;   // [g][row=grp][j0]
        float4 s = *reinterpret_cast<const float4*>(pr);
        #pragma unroll
        for (int g = 1; g < 8; ++g) {
            const float4 p = *reinterpret_cast<const float4*>(
                pr + g * (NBMAX * Hh));
            s.x += p.x; s.y += p.y; s.z += p.z; s.w += p.w;
        }
        float4 o;
        o.x = fast_tanh(s.x + xe_cur.x);
        o.y = fast_tanh(s.y + xe_cur.y);
        o.z = fast_tanh(s.z + xe_cur.z);
        o.w = fast_tanh(s.w + xe_cur.w);
        float* hn = hT + (CUR ^ 1) * (NBMAX * Hh) + grp * Hh + j0;
        *reinterpret_cast<float4*>(hn) = o;
    }
    xe_cur = xe_nxt;

    __syncthreads();
}

template <int NB>
__device__ __forceinline__ void rnn_loop_body(
    int rowStart,
    const float* __restrict__ W_hh,
    const float* __restrict__ W_fc,
    const float* __restrict__ b_fc,
    float* __restrict__ out,
    float* hT, float* part)
{
    const int tid = threadIdx.x;
    const int jq  = tid & 31;       // lane -> j quad
    const int grp = tid >> 5;       // warp -> k slice [16*grp, 16*grp+16)
    const int j0  = 4 * jq;

    for (int idx = tid; idx < 2 * NBMAX * Hh; idx += NTH) hT[idx] = 0.0f;

    // Weights: 4 j rows x 16 k, packed over k (one-time strided LDG, tiny)
    ull wk[4][8];
    #pragma unroll
    for (int jj = 0; jj < 4; ++jj) {
        const float* wr = W_hh + (j0 + jj) * Hh + grp * 16;
        #pragma unroll
        for (int p = 0; p < 8; ++p)
            wk[jj][p] = *reinterpret_cast<const ull*>(wr + 2 * p);
    }

    const bool fin = (grp < NB);
    const int myRow = fin ? (rowStart + grp) : rowStart;
    const float* xe_p = xe_buf + ((size_t)myRow * Tt) * Hh + j0;
    float4 xe_cur = make_float4(0.f, 0.f, 0.f, 0.f);
    if (fin) xe_cur = *reinterpret_cast<const float4*>(xe_p);

    // Loop-invariant posting base: part[grp][·][j0]
    float* postp = part + (grp * NBMAX) * Hh + j0;

    __syncthreads();

    #pragma unroll 1
    for (int t = 0; t < Tt; t += 2) {
        rnn_step<NB, 0>(t,     grp, j0, fin, wk, hT, part, postp, xe_p, xe_cur);
        xe_p += Hh;
        rnn_step<NB, 1>(t + 1, grp, j0, fin, wk, hT, part, postp, xe_p, xe_cur);
        xe_p += Hh;
    }

    // ---- Final FC: out[b][o] = b_fc[o] + sum_j W_fc[o][j] * h_last[b][j] ----
    // Tt even -> last h landed in buffer 0. Layout [row][j].
    const float* hlast = hT;
    if (tid < NB * Oo) {
        const int b = tid / Oo;
        const int o = tid - b * Oo;
        float s = b_fc[o];
        const float* wp = W_fc + o * Hh;
        const float* hp = hlast + b * Hh;
        #pragma unroll 8
        for (int jj = 0; jj < Hh; ++jj)
            s = fmaf(wp[jj], hp[jj], s);
        out[(rowStart + b) * Oo + o] = s;
    }
}

#define LNBLK 296   // 2x148; 4-row CTAs pair with 3-row CTAs -> 7 rows/SM

__global__ void __launch_bounds__(NTH, 2)
rnn_loop_kernel(const float* __restrict__ W_hh,
                const float* __restrict__ W_fc,
                const float* __restrict__ b_fc,
                float* __restrict__ out)
{
    __shared__ float sm[2 * NBMAX * Hh + 8 * NBMAX * Hh];  // hT 4KB + part 16KB
    float* hT   = sm;
    float* part = sm + 2 * NBMAX * Hh;

    const int bid = blockIdx.x;
    if (bid < 136) {
        rnn_loop_body<4>(4 * bid, W_hh, W_fc, b_fc, out, hT, part);
    } else if (bid < 148) {
        rnn_loop_body<3>(544 + 3 * (bid - 136), W_hh, W_fc, b_fc, out, hT, part);
    } else {
        rnn_loop_body<3>(580 + 3 * (bid - 148), W_hh, W_fc, b_fc, out, hT, part);
    }
}

extern "C" void kernel_launch(void* const* d_in, const int* in_sizes, int n_in,
                              void* d_out, int out_size)
{
    const float* x   = (const float*)d_in[0];
    const float* Wih = (const float*)d_in[1];
    const float* bih = (const float*)d_in[2];
    const float* Whh = (const float*)d_in[3];
    const float* bhh = (const float*)d_in[4];
    const float* Wfc = (const float*)d_in[5];
    const float* bfc = (const float*)d_in[6];
    float* out = (float*)d_out;

    xe_prepass_kernel<<<4096, NTH>>>(x, Wih, bih, bhh);
    rnn_loop_kernel<<<LNBLK, NTH>>>(Whh, Wfc, bfc, out);
}

// round 16
// speedup vs baseline: 1.5964x; 1.5964x over previous
#include <cuda_runtime.h>
#include <cstdint>
#include <cstddef>

// Problem dims (fixed by the reference)
#define Bt 1024
#define Tt 512
#define Ii 45
#define Hh 128
#define Oo 45

#define NTH 256
#define NBMAX 4
typedef unsigned long long ull;

// 256 MB scratch: xe[bt][j] = b_ih[j] + b_hh[j] + sum_i x[bt][i]*W_ih[j][i]
__device__ float xe_buf[(size_t)Bt * Tt * Hh];

__device__ __forceinline__ void fma2(ull& acc, ull a, ull b) {
    asm("fma.rn.f32x2 %0, %1, %2, %0;" : "+l"(acc) : "l"(a), "l"(b));
}
__device__ __forceinline__ float2 unpack2(ull d) {
    unsigned lo, hi;
    asm("mov.b64 {%0, %1}, %2;" : "=r"(lo), "=r"(hi) : "l"(d));
    return make_float2(__uint_as_float(lo), __uint_as_float(hi));
}
__device__ __forceinline__ ull pack2f(float lo, float hi) {
    ull d;
    asm("mov.b64 %0, {%1, %2};" : "=l"(d)
        : "r"(__float_as_uint(lo)), "r"(__float_as_uint(hi)));
    return d;
}

// tanh(x) = 1 - 2/(exp(2x)+1): ~1e-6 abs err, exact +/-1 saturation.
__device__ __forceinline__ float fast_tanh(float x) {
    float e = __expf(2.0f * x);
    return 1.0f - __fdividef(2.0f, e + 1.0f);
}

// ============================================================================
// Pre-pass (unchanged from R14)
// ============================================================================
__global__ void __launch_bounds__(NTH, 2)
xe_prepass_kernel(const float* __restrict__ x,
                  const float* __restrict__ W_ih,
                  const float* __restrict__ b_ih,
                  const float* __restrict__ b_hh)
{
    __shared__ float xs[128 * 48];
    __shared__ ull   wp2[24 * 128];

    const int tid = threadIdx.x;
    const int jp  = tid & 63, btg = tid >> 6;
    const int j0  = 2 * jp, j1 = j0 + 1;
    const size_t btBase = (size_t)blockIdx.x * 128;

    for (int idx = tid; idx < 128 * 48; idx += NTH) {
        const int btl = idx / 48, ii = idx - btl * 48;
        xs[idx] = (ii < Ii) ? x[(btBase + btl) * Ii + ii] : 0.0f;
    }
    for (int idx = tid; idx < 128 * 24; idx += NTH) {
        const int jj = idx / 24, p = idx - jj * 24;
        const int ia = 2 * p, ib = ia + 1;
        const float w0 = (ia < Ii) ? W_ih[jj * Ii + ia] : 0.0f;
        const float w1 = (ib < Ii) ? W_ih[jj * Ii + ib] : 0.0f;
        wp2[p * 128 + jj] = pack2f(w0, w1);
    }
    const float bi0 = b_ih[j0] + b_hh[j0];
    const float bi1 = b_ih[j1] + b_hh[j1];
    __syncthreads();

    ull wA[24], wB[24];
    #pragma unroll
    for (int p = 0; p < 24; ++p) {
        wA[p] = wp2[p * 128 + j0];
        wB[p] = wp2[p * 128 + j1];
    }

    for (int c = 0; c < 8; ++c) {
        const int bt0 = btg * 32 + c * 4;
        ull aA[4] = {0ull, 0ull, 0ull, 0ull};
        ull aB[4] = {0ull, 0ull, 0ull, 0ull};

        #pragma unroll
        for (int q = 0; q < 12; ++q) {
            #pragma unroll
            for (int r = 0; r < 4; ++r) {
                const ulonglong2 v = *reinterpret_cast<const ulonglong2*>(
                    xs + (bt0 + r) * 48 + q * 4);
                fma2(aA[r], wA[2 * q], v.x); fma2(aA[r], wA[2 * q + 1], v.y);
                fma2(aB[r], wB[2 * q], v.x); fma2(aB[r], wB[2 * q + 1], v.y);
            }
        }
        #pragma unroll
        for (int r = 0; r < 4; ++r) {
            const float2 fA = unpack2(aA[r]);
            const float2 fB = unpack2(aB[r]);
            float2 o;
            o.x = bi0 + fA.x + fA.y;
            o.y = bi1 + fB.x + fB.y;
            *reinterpret_cast<float2*>(
                xe_buf + (btBase + bt0 + r) * Hh + j0) = o;
        }
    }
}

// ============================================================================
// Recurrence loop: R14 body verbatim, with ONLY two micro-changes:
//   (1) double buffer via pointer swap (no per-step base recompute)
//   (2) xe pointer strength reduction (+= Hh per step)
// ============================================================================
template <int NB>
__device__ __forceinline__ void rnn_loop_body(
    int rowStart,
    const float* __restrict__ W_hh,
    const float* __restrict__ W_fc,
    const float* __restrict__ b_fc,
    float* __restrict__ out,
    float* hT, float* part)
{
    const int tid = threadIdx.x;
    const int jq  = tid & 31;       // lane -> j quad
    const int grp = tid >> 5;       // warp -> k slice [16*grp, 16*grp+16)
    const int j0  = 4 * jq;

    for (int idx = tid; idx < 2 * NBMAX * Hh; idx += NTH) hT[idx] = 0.0f;

    // Weights: 4 j rows x 16 k, packed over k (one-time strided LDG, tiny)
    ull wk[4][8];
    #pragma unroll
    for (int jj = 0; jj < 4; ++jj) {
        const float* wr = W_hh + (j0 + jj) * Hh + grp * 16;
        #pragma unroll
        for (int p = 0; p < 8; ++p)
            wk[jj][p] = *reinterpret_cast<const ull*>(wr + 2 * p);
    }

    // Warp grp finishes row grp (if grp < NB)
    const bool fin = (grp < NB);
    const int myRow = fin ? (rowStart + grp) : rowStart;
    const float* xe_p = xe_buf + ((size_t)myRow * Tt) * Hh + j0;
    float4 xe_cur = make_float4(0.f, 0.f, 0.f, 0.f);
    if (fin) xe_cur = *reinterpret_cast<const float4*>(xe_p);

    // Double-buffer pointers (swapped each step; no per-step recompute)
    const float* hcur = hT + grp * 16;
    float*       hnxt = hT + NBMAX * Hh;

    __syncthreads();

    #pragma unroll 1
    for (int t = 0; t < Tt; ++t) {
        // Prefetch next step's xe (finishing warps only; hidden behind FMAs)
        float4 xe_nxt = make_float4(0.f, 0.f, 0.f, 0.f);
        if (fin && t + 1 < Tt)
            xe_nxt = *reinterpret_cast<const float4*>(xe_p + Hh);
        xe_p += Hh;

        // acc[jj][r]: packed (even-k, odd-k) partial sums
        ull acc[4][NB];
        #pragma unroll
        for (int jj = 0; jj < 4; ++jj)
            #pragma unroll
            for (int r = 0; r < NB; ++r) acc[jj][r] = 0ull;

        // Inner: 4 k-quads x NB rows; each broadcast LDS.128 feeds 8 fma2
        #pragma unroll
        for (int q = 0; q < 4; ++q) {
            #pragma unroll
            for (int r = 0; r < NB; ++r) {
                const ulonglong2 v =
                    *reinterpret_cast<const ulonglong2*>(hcur + r * Hh + q * 4);
                #pragma unroll
                for (int jj = 0; jj < 4; ++jj) {
                    fma2(acc[jj][r], wk[jj][2 * q], v.x);
                    fma2(acc[jj][r], wk[jj][2 * q + 1], v.y);
                }
            }
        }

        // Collapse packed lanes to scalars; post float4 partials (not own row)
        float4 own = make_float4(0.f, 0.f, 0.f, 0.f);
        #pragma unroll
        for (int r = 0; r < NB; ++r) {
            float4 s;
            { const float2 f = unpack2(acc[0][r]); s.x = f.x + f.y; }
            { const float2 f = unpack2(acc[1][r]); s.y = f.x + f.y; }
            { const float2 f = unpack2(acc[2][r]); s.z = f.x + f.y; }
            { const float2 f = unpack2(acc[3][r]); s.w = f.x + f.y; }
            if (r == grp) own = s;
            else *reinterpret_cast<float4*>(part + (grp * NBMAX + r) * Hh + j0) = s;
        }
        __syncthreads();

        // Finish row grp: add 7 other groups' partials + xe, tanh, store h
        if (fin) {
            const int r = grp;
            float4 s = own;
            #pragma unroll
            for (int g = 0; g < 8; ++g) {
                if (g != grp) {
                    const float4 p = *reinterpret_cast<const float4*>(
                        part + (g * NBMAX + r) * Hh + j0);
                    s.x += p.x; s.y += p.y; s.z += p.z; s.w += p.w;
                }
            }
            float4 o;
            o.x = fast_tanh(s.x + xe_cur.x);
            o.y = fast_tanh(s.y + xe_cur.y);
            o.z = fast_tanh(s.z + xe_cur.z);
            o.w = fast_tanh(s.w + xe_cur.w);
            *reinterpret_cast<float4*>(hnxt + r * Hh + j0) = o;
        }
        xe_cur = xe_nxt;

        // Swap double-buffer pointers
        const float* tmp = hcur;
        hcur = hnxt + grp * 16;
        hnxt = const_cast<float*>(tmp) - grp * 16;

        __syncthreads();
    }

    // ---- Final FC: out[b][o] = b_fc[o] + sum_j W_fc[o][j] * h_last[b][j] ----
    // Tt even -> last h landed in buffer 0. Layout [row][j].
    const float* hlast = hT;
    if (tid < NB * Oo) {
        const int b = tid / Oo;
        const int o = tid - b * Oo;
        float s = b_fc[o];
        const float* wp = W_fc + o * Hh;
        const float* hp = hlast + b * Hh;
        #pragma unroll 8
        for (int jj = 0; jj < Hh; ++jj)
            s = fmaf(wp[jj], hp[jj], s);
        out[(rowStart + b) * Oo + o] = s;
    }
}

#define LNBLK 296   // 2x148; 4-row CTAs pair with 3-row CTAs -> 7 rows/SM

__global__ void __launch_bounds__(NTH, 2)
rnn_loop_kernel(const float* __restrict__ W_hh,
                const float* __restrict__ W_fc,
                const float* __restrict__ b_fc,
                float* __restrict__ out)
{
    __shared__ float sm[2 * NBMAX * Hh + 8 * NBMAX * Hh];  // hT 4KB + part 16KB
    float* hT   = sm;
    float* part = sm + 2 * NBMAX * Hh;

    const int bid = blockIdx.x;
    if (bid < 136) {
        rnn_loop_body<4>(4 * bid, W_hh, W_fc, b_fc, out, hT, part);
    } else if (bid < 148) {
        rnn_loop_body<3>(544 + 3 * (bid - 136), W_hh, W_fc, b_fc, out, hT, part);
    } else {
        rnn_loop_body<3>(580 + 3 * (bid - 148), W_hh, W_fc, b_fc, out, hT, part);
    }
}

extern "C" void kernel_launch(void* const* d_in, const int* in_sizes, int n_in,
                              void* d_out, int out_size)
{
    const float* x   = (const float*)d_in[0];
    const float* Wih = (const float*)d_in[1];
    const float* bih = (const float*)d_in[2];
    const float* Whh = (const float*)d_in[3];
    const float* bhh = (const float*)d_in[4];
    const float* Wfc = (const float*)d_in[5];
    const float* bfc = (const float*)d_in[6];
    float* out = (float*)d_out;

    xe_prepass_kernel<<<4096, NTH>>>(x, Wih, bih, bhh);
    rnn_loop_kernel<<<LNBLK, NTH>>>(Whh, Wfc, bfc, out);
}

// round 17
// speedup vs baseline: 1.6052x; 1.0055x over previous
#include <cuda_runtime.h>
#include <cstdint>
#include <cstddef>

// Problem dims (fixed by the reference)
#define Bt 1024
#define Tt 512
#define Ii 45
#define Hh 128
#define Oo 45

#define NTH 256
#define NBMAX 4
typedef unsigned long long ull;

// 256 MB scratch (+128 slack): xe[bt][j] = b_ih[j]+b_hh[j]+sum_i x[bt][i]*W_ih[j][i]
__device__ float xe_buf[(size_t)Bt * Tt * Hh + Hh];

__device__ __forceinline__ void fma2(ull& acc, ull a, ull b) {
    asm("fma.rn.f32x2 %0, %1, %2, %0;" : "+l"(acc) : "l"(a), "l"(b));
}
__device__ __forceinline__ float2 unpack2(ull d) {
    unsigned lo, hi;
    asm("mov.b64 {%0, %1}, %2;" : "=r"(lo), "=r"(hi) : "l"(d));
    return make_float2(__uint_as_float(lo), __uint_as_float(hi));
}
__device__ __forceinline__ ull pack2f(float lo, float hi) {
    ull d;
    asm("mov.b64 %0, {%1, %2};" : "=l"(d)
        : "r"(__float_as_uint(lo)), "r"(__float_as_uint(hi)));
    return d;
}

// tanh(x) = 1 - 2/(exp(2x)+1): ~1e-6 abs err, exact +/-1 saturation.
__device__ __forceinline__ float fast_tanh(float x) {
    float e = __expf(2.0f * x);
    return 1.0f - __fdividef(2.0f, e + 1.0f);
}

// ============================================================================
// Pre-pass v3: i trimmed to 23 pairs (11 full quads + 1 pair tail).
// xs row stride stays 48 floats for 16B quad alignment; i 46..47 zero.
// ============================================================================
__global__ void __launch_bounds__(NTH, 2)
xe_prepass_kernel(const float* __restrict__ x,
                  const float* __restrict__ W_ih,
                  const float* __restrict__ b_ih,
                  const float* __restrict__ b_hh)
{
    __shared__ float xs[128 * 48];   // [bt_local][i48]
    __shared__ ull   wp2[23 * 128];  // [i_pair][j] packed pairs

    const int tid = threadIdx.x;
    const int jp  = tid & 63, btg = tid >> 6;
    const int j0  = 2 * jp, j1 = j0 + 1;
    const size_t btBase = (size_t)blockIdx.x * 128;

    // Stage x tile (i >= 45 zero-padded; stride 48 keeps quads 16B-aligned)
    for (int idx = tid; idx < 128 * 48; idx += NTH) {
        const int btl = idx / 48, ii = idx - btl * 48;
        xs[idx] = (ii < Ii) ? x[(btBase + btl) * Ii + ii] : 0.0f;
    }
    // Stage W_ih as 23 packed pairs per j (pair 22 = (w[44], w[45]=0))
    for (int idx = tid; idx < 128 * 23; idx += NTH) {
        const int jj = idx / 23, p = idx - jj * 23;
        const int ia = 2 * p, ib = ia + 1;
        const float w0 = (ia < Ii) ? W_ih[jj * Ii + ia] : 0.0f;
        const float w1 = (ib < Ii) ? W_ih[jj * Ii + ib] : 0.0f;
        wp2[p * 128 + jj] = pack2f(w0, w1);
    }
    const float bi0 = b_ih[j0] + b_hh[j0];
    const float bi1 = b_ih[j1] + b_hh[j1];
    __syncthreads();

    ull wA[23], wB[23];
    #pragma unroll
    for (int p = 0; p < 23; ++p) {
        wA[p] = wp2[p * 128 + j0];
        wB[p] = wp2[p * 128 + j1];
    }

    for (int c = 0; c < 8; ++c) {
        const int bt0 = btg * 32 + c * 4;
        ull aA[4] = {0ull, 0ull, 0ull, 0ull};
        ull aB[4] = {0ull, 0ull, 0ull, 0ull};

        // 11 full i-quads (i 0..43)
        #pragma unroll
        for (int q = 0; q < 11; ++q) {
            #pragma unroll
            for (int r = 0; r < 4; ++r) {
                const ulonglong2 v = *reinterpret_cast<const ulonglong2*>(
                    xs + (bt0 + r) * 48 + q * 4);
                fma2(aA[r], wA[2 * q], v.x); fma2(aA[r], wA[2 * q + 1], v.y);
                fma2(aB[r], wB[2 * q], v.x); fma2(aB[r], wB[2 * q + 1], v.y);
            }
        }
        // Tail pair (i 44..45; i45 weight is zero-padded)
        #pragma unroll
        for (int r = 0; r < 4; ++r) {
            const ull v = *reinterpret_cast<const ull*>(xs + (bt0 + r) * 48 + 44);
            fma2(aA[r], wA[22], v);
            fma2(aB[r], wB[22], v);
        }

        #pragma unroll
        for (int r = 0; r < 4; ++r) {
            const float2 fA = unpack2(aA[r]);
            const float2 fB = unpack2(aB[r]);
            float2 o;
            o.x = bi0 + fA.x + fA.y;
            o.y = bi1 + fB.x + fB.y;
            *reinterpret_cast<float2*>(
                xe_buf + (btBase + bt0 + r) * Hh + j0) = o;
        }
    }
}

// ============================================================================
// Recurrence loop: R16 verbatim (best measured: 536 us ncu).
// ============================================================================
template <int NB>
__device__ __forceinline__ void rnn_loop_body(
    int rowStart,
    const float* __restrict__ W_hh,
    const float* __restrict__ W_fc,
    const float* __restrict__ b_fc,
    float* __restrict__ out,
    float* hT, float* part)
{
    const int tid = threadIdx.x;
    const int jq  = tid & 31;       // lane -> j quad
    const int grp = tid >> 5;       // warp -> k slice [16*grp, 16*grp+16)
    const int j0  = 4 * jq;

    for (int idx = tid; idx < 2 * NBMAX * Hh; idx += NTH) hT[idx] = 0.0f;

    // Weights: 4 j rows x 16 k, packed over k (one-time strided LDG, tiny)
    ull wk[4][8];
    #pragma unroll
    for (int jj = 0; jj < 4; ++jj) {
        const float* wr = W_hh + (j0 + jj) * Hh + grp * 16;
        #pragma unroll
        for (int p = 0; p < 8; ++p)
            wk[jj][p] = *reinterpret_cast<const ull*>(wr + 2 * p);
    }

    // Warp grp finishes row grp (if grp < NB)
    const bool fin = (grp < NB);
    const int myRow = fin ? (rowStart + grp) : rowStart;
    const float* xe_p = xe_buf + ((size_t)myRow * Tt) * Hh + j0;
    float4 xe_cur = make_float4(0.f, 0.f, 0.f, 0.f);
    if (fin) xe_cur = *reinterpret_cast<const float4*>(xe_p);

    // Double-buffer pointers (swapped each step; no per-step recompute)
    const float* hcur = hT + grp * 16;
    float*       hnxt = hT + NBMAX * Hh;

    __syncthreads();

    #pragma unroll 1
    for (int t = 0; t < Tt; ++t) {
        // Prefetch next step's xe (finishing warps only; hidden behind FMAs)
        float4 xe_nxt = make_float4(0.f, 0.f, 0.f, 0.f);
        if (fin && t + 1 < Tt)
            xe_nxt = *reinterpret_cast<const float4*>(xe_p + Hh);
        xe_p += Hh;

        // acc[jj][r]: packed (even-k, odd-k) partial sums
        ull acc[4][NB];
        #pragma unroll
        for (int jj = 0; jj < 4; ++jj)
            #pragma unroll
            for (int r = 0; r < NB; ++r) acc[jj][r] = 0ull;

        // Inner: 4 k-quads x NB rows; each broadcast LDS.128 feeds 8 fma2
        #pragma unroll
        for (int q = 0; q < 4; ++q) {
            #pragma unroll
            for (int r = 0; r < NB; ++r) {
                const ulonglong2 v =
                    *reinterpret_cast<const ulonglong2*>(hcur + r * Hh + q * 4);
                #pragma unroll
                for (int jj = 0; jj < 4; ++jj) {
                    fma2(acc[jj][r], wk[jj][2 * q], v.x);
                    fma2(acc[jj][r], wk[jj][2 * q + 1], v.y);
                }
            }
        }

        // Collapse packed lanes to scalars; post float4 partials (not own row)
        float4 own = make_float4(0.f, 0.f, 0.f, 0.f);
        #pragma unroll
        for (int r = 0; r < NB; ++r) {
            float4 s;
            { const float2 f = unpack2(acc[0][r]); s.x = f.x + f.y; }
            { const float2 f = unpack2(acc[1][r]); s.y = f.x + f.y; }
            { const float2 f = unpack2(acc[2][r]); s.z = f.x + f.y; }
            { const float2 f = unpack2(acc[3][r]); s.w = f.x + f.y; }
            if (r == grp) own = s;
            else *reinterpret_cast<float4*>(part + (grp * NBMAX + r) * Hh + j0) = s;
        }
        __syncthreads();

        // Finish row grp: add 7 other groups' partials + xe, tanh, store h
        if (fin) {
            const int r = grp;
            float4 s = own;
            #pragma unroll
            for (int g = 0; g < 8; ++g) {
                if (g != grp) {
                    const float4 p = *reinterpret_cast<const float4*>(
                        part + (g * NBMAX + r) * Hh + j0);
                    s.x += p.x; s.y += p.y; s.z += p.z; s.w += p.w;
                }
            }
            float4 o;
            o.x = fast_tanh(s.x + xe_cur.x);
            o.y = fast_tanh(s.y + xe_cur.y);
            o.z = fast_tanh(s.z + xe_cur.z);
            o.w = fast_tanh(s.w + xe_cur.w);
            *reinterpret_cast<float4*>(hnxt + r * Hh + j0) = o;
        }
        xe_cur = xe_nxt;

        // Swap double-buffer pointers
        const float* tmp = hcur;
        hcur = hnxt + grp * 16;
        hnxt = const_cast<float*>(tmp) - grp * 16;

        __syncthreads();
    }

    // ---- Final FC: out[b][o] = b_fc[o] + sum_j W_fc[o][j] * h_last[b][j] ----
    // Tt even -> last h landed in buffer 0. Layout [row][j].
    const float* hlast = hT;
    if (tid < NB * Oo) {
        const int b = tid / Oo;
        const int o = tid - b * Oo;
        float s = b_fc[o];
        const float* wp = W_fc + o * Hh;
        const float* hp = hlast + b * Hh;
        #pragma unroll 8
        for (int jj = 0; jj < Hh; ++jj)
            s = fmaf(wp[jj], hp[jj], s);
        out[(rowStart + b) * Oo + o] = s;
    }
}

#define LNBLK 296   // 2x148; 4-row CTAs pair with 3-row CTAs -> 7 rows/SM

__global__ void __launch_bounds__(NTH, 2)
rnn_loop_kernel(const float* __restrict__ W_hh,
                const float* __restrict__ W_fc,
                const float* __restrict__ b_fc,
                float* __restrict__ out)
{
    __shared__ float sm[2 * NBMAX * Hh + 8 * NBMAX * Hh];  // hT 4KB + part 16KB
    float* hT   = sm;
    float* part = sm + 2 * NBMAX * Hh;

    const int bid = blockIdx.x;
    if (bid < 136) {
        rnn_loop_body<4>(4 * bid, W_hh, W_fc, b_fc, out, hT, part);
    } else if (bid < 148) {
        rnn_loop_body<3>(544 + 3 * (bid - 136), W_hh, W_fc, b_fc, out, hT, part);
    } else {
        rnn_loop_body<3>(580 + 3 * (bid - 148), W_hh, W_fc, b_fc, out, hT, part);
    }
}

extern "C" void kernel_launch(void* const* d_in, const int* in_sizes, int n_in,
                              void* d_out, int out_size)
{
    const float* x   = (const float*)d_in[0];
    const float* Wih = (const float*)d_in[1];
    const float* bih = (const float*)d_in[2];
    const float* Whh = (const float*)d_in[3];
    const float* bhh = (const float*)d_in[4];
    const float* Wfc = (const float*)d_in[5];
    const float* bfc = (const float*)d_in[6];
    float* out = (float*)d_out;

    xe_prepass_kernel<<<4096, NTH>>>(x, Wih, bih, bhh);
    rnn_loop_kernel<<<LNBLK, NTH>>>(Whh, Wfc, bfc, out);
}